// round 15
// baseline (speedup 1.0000x reference)
#include <cuda_runtime.h>
#include <cuda_bf16.h>
#include <cuda_fp16.h>
#include <math.h>
#include <stdint.h>

#define NN 30000
#define EE 480000
#define ET (EE + NN)
#define FIN 4096
#define HC 512
#define HEADS 4
#define HID 128
#define CLS 6

// ---------------- scratch (static device globals) ---------------------------
__device__ __half   g_h1h[(size_t)NN * HC];    // fp16 h1 (sole copy)
__device__ float    g_out1[(size_t)NN * HC];
__device__ __half   g_w1h[(size_t)HC * FIN];   // W1^T, fp16, K-major
__device__ float    g_as1[NN * HEADS];
__device__ float    g_ad1[NN * HEADS];
__device__ float    g_h2[NN * CLS];
__device__ float    g_as2[NN];
__device__ float    g_ad2[NN];
__device__ int      g_deg[NN];
__device__ int      g_off[NN + 1];
__device__ int      g_pos[NN];
__device__ int      g_esrc[ET];

__device__ __forceinline__ float lrelu(float v) { return v > 0.f ? v : 0.2f * v; }
__device__ __forceinline__ void edge_sd(const int* __restrict__ ei, int e,
                                        int& s, int& d) {
    if (e < EE) { s = ei[e]; d = ei[EE + e]; } else { s = d = e - EE; }
}
__device__ __forceinline__ uint32_t smem_u32(const void* p) {
    uint32_t a;
    asm("{ .reg .u64 t; cvta.to.shared.u64 t, %1; cvt.u32.u64 %0, t; }"
        : "=r"(a) : "l"(p));
    return a;
}
__device__ __forceinline__ void cp16(uint32_t saddr, const void* g, int bytes) {
    asm volatile("cp.async.ca.shared.global [%0], [%1], 16, %2;"
                 :: "r"(saddr), "l"(g), "r"(bytes));
}
__device__ __forceinline__ unsigned pack_h2(float lo, float hi) {
    unsigned d;
    asm("cvt.rn.f16x2.f32 %0, %1, %2;" : "=r"(d) : "f"(hi), "f"(lo));
    return d;
}

// ---------------- CSR build --------------------------------------------------
__global__ void zero_deg_kernel() {
    int i = blockIdx.x * blockDim.x + threadIdx.x;
    if (i < NN) g_deg[i] = 0;
}
__global__ void count_kernel(const int* __restrict__ ei) {
    int e = blockIdx.x * blockDim.x + threadIdx.x;
    if (e >= ET) return;
    int s, d; edge_sd(ei, e, s, d);
    atomicAdd(&g_deg[d], 1);
}
__global__ void scan_kernel() {
    __shared__ int partial[1024];
    const int t = threadIdx.x;
    const int CH = (NN + 1023) / 1024;
    const int base = t * CH;
    int sum = 0;
    for (int c = 0; c < CH; c++) { int i = base + c; if (i < NN) sum += g_deg[i]; }
    partial[t] = sum;
    __syncthreads();
    for (int off = 1; off < 1024; off <<= 1) {
        int v = (t >= off) ? partial[t - off] : 0;
        __syncthreads();
        partial[t] += v;
        __syncthreads();
    }
    int acc = partial[t] - sum;
    for (int c = 0; c < CH; c++) {
        int i = base + c;
        if (i < NN) { g_off[i] = acc; g_pos[i] = acc; acc += g_deg[i]; }
    }
    if (t == 0) g_off[NN] = ET;
}
__global__ void scatter_kernel(const int* __restrict__ ei) {
    int e = blockIdx.x * blockDim.x + threadIdx.x;
    if (e >= ET) return;
    int s, d; edge_sd(ei, e, s, d);
    int p = atomicAdd(&g_pos[d], 1);
    g_esrc[p] = s;
}

// ---------- transpose W1 -> fp16 (32x32 shared tiles, coalesced) ------------
__global__ __launch_bounds__(256) void w1t_kernel(const float* __restrict__ W1) {
    __shared__ float tile[32][33];
    const int k0 = blockIdx.y * 32;
    const int n0 = blockIdx.x * 32;
    const int tx = threadIdx.x & 31;
    const int ty = threadIdx.x >> 5;
#pragma unroll
    for (int r = 0; r < 4; r++) {
        int k = k0 + ty + r * 8;
        tile[ty + r * 8][tx] = W1[(size_t)k * HC + n0 + tx];
    }
    __syncthreads();
#pragma unroll
    for (int r = 0; r < 4; r++) {
        int n = n0 + ty + r * 8;
        g_w1h[(size_t)n * FIN + k0 + tx] = __float2half_rn(tile[tx][ty + r * 8]);
    }
}

// ---------------- GEMM1 (mma.sync fp16): h1 = x @ W1 ------------------------
// CTA 128x256, BK=64, 3-stage cp.async, 8 warps, warp 64x64, mma m16n8k16.
#define BM 128
#define BN 256
#define BK2 64
#define ASTR 68                      // A row stride, floats
#define BSTRH 72                     // B row stride, halves (conflict-free)
#define A_STAGE (BM * ASTR)          // floats
#define B_STAGE_H (BN * BSTRH)       // halves
#define SMEM_BYTES (3 * (A_STAGE * 4 + B_STAGE_H * 2))   // 215040

__global__ __launch_bounds__(256, 1) void gemm1_tc(const float* __restrict__ A) {
    extern __shared__ float sm[];
    float*  Asm  = sm;
    __half* Bsmh = (__half*)(sm + 3 * A_STAGE);
    const int t    = threadIdx.x;
    const int m0   = blockIdx.y * BM;
    const int n0   = blockIdx.x * BN;
    const int wid  = t >> 5;
    const int lane = t & 31;
    const int gid  = lane >> 2;
    const int tid4 = lane & 3;
    const int wm   = (wid >> 2) * 64;
    const int wn   = (wid & 3) * 64;

    float acc[4][8][4];
#pragma unroll
    for (int i = 0; i < 4; i++)
#pragma unroll
        for (int j = 0; j < 8; j++)
#pragma unroll
            for (int r = 0; r < 4; r++) acc[i][j][r] = 0.f;

    auto load_stage = [&](int s, int k0) {
        uint32_t ab = smem_u32(Asm + s * A_STAGE);
        uint32_t bb = smem_u32(Bsmh + s * B_STAGE_H);
        // A: 128 rows x 64 floats = 2048 x 16B chunks
#pragma unroll
        for (int j = 0; j < 8; j++) {
            int idx = j * 256 + t;
            int row = idx >> 4, c4 = (idx & 15) << 2;
            int gr = m0 + row;
            cp16(ab + (row * ASTR + c4) * 4,
                 A + (size_t)gr * FIN + k0 + c4, gr < NN ? 16 : 0);
        }
        // B: 256 rows x 64 halves = 2048 x 16B chunks
#pragma unroll
        for (int j = 0; j < 8; j++) {
            int idx = j * 256 + t;
            int row = idx >> 3, c8 = (idx & 7) << 3;
            cp16(bb + (row * BSTRH + c8) * 2,
                 g_w1h + (size_t)(n0 + row) * FIN + k0 + c8, 16);
        }
        asm volatile("cp.async.commit_group;");
    };

    load_stage(0, 0);
    load_stage(1, BK2);

    const int NT = FIN / BK2;          // 64
    for (int kt = 0; kt < NT; kt++) {
        if (kt + 1 < NT) asm volatile("cp.async.wait_group 1;");
        else             asm volatile("cp.async.wait_group 0;");
        __syncthreads();
        const int s = kt % 3;
        const float*  as = Asm  + s * A_STAGE;
        const __half* bs = Bsmh + s * B_STAGE_H;

#pragma unroll
        for (int kk = 0; kk < BK2; kk += 16) {
            unsigned af[4][4], bf[8][2];
#pragma unroll
            for (int mt = 0; mt < 4; mt++) {
                int r = wm + mt * 16 + gid;
                float2 v0 = *(const float2*)&as[r * ASTR + kk + tid4 * 2];
                float2 v1 = *(const float2*)&as[(r + 8) * ASTR + kk + tid4 * 2];
                float2 v2 = *(const float2*)&as[r * ASTR + kk + 8 + tid4 * 2];
                float2 v3 = *(const float2*)&as[(r + 8) * ASTR + kk + 8 + tid4 * 2];
                af[mt][0] = pack_h2(v0.x, v0.y);
                af[mt][1] = pack_h2(v1.x, v1.y);
                af[mt][2] = pack_h2(v2.x, v2.y);
                af[mt][3] = pack_h2(v3.x, v3.y);
            }
#pragma unroll
            for (int nt = 0; nt < 8; nt++) {
                int c = wn + nt * 8 + gid;
                bf[nt][0] = *(const unsigned*)&bs[c * BSTRH + kk + tid4 * 2];
                bf[nt][1] = *(const unsigned*)&bs[c * BSTRH + kk + 8 + tid4 * 2];
            }
#pragma unroll
            for (int mt = 0; mt < 4; mt++)
#pragma unroll
                for (int nt = 0; nt < 8; nt++) {
                    asm volatile(
                        "mma.sync.aligned.m16n8k16.row.col.f32.f16.f16.f32 "
                        "{%0,%1,%2,%3}, {%4,%5,%6,%7}, {%8,%9}, {%0,%1,%2,%3};"
                        : "+f"(acc[mt][nt][0]), "+f"(acc[mt][nt][1]),
                          "+f"(acc[mt][nt][2]), "+f"(acc[mt][nt][3])
                        : "r"(af[mt][0]), "r"(af[mt][1]),
                          "r"(af[mt][2]), "r"(af[mt][3]),
                          "r"(bf[nt][0]), "r"(bf[nt][1]));
                }
        }
        if (kt + 2 < NT) load_stage((kt + 2) % 3, (kt + 2) * BK2);
    }

    // epilogue: fp16-only h1
#pragma unroll
    for (int mt = 0; mt < 4; mt++) {
        int r1 = m0 + wm + mt * 16 + gid;
        int r2 = r1 + 8;
#pragma unroll
        for (int nt = 0; nt < 8; nt++) {
            int c = n0 + wn + nt * 8 + tid4 * 2;
            if (r1 < NN)
                *(unsigned*)(g_h1h + (size_t)r1 * HC + c) =
                    pack_h2(acc[mt][nt][0], acc[mt][nt][1]);
            if (r2 < NN)
                *(unsigned*)(g_h1h + (size_t)r2 * HC + c) =
                    pack_h2(acc[mt][nt][2], acc[mt][nt][3]);
        }
    }
}

// ---------------- per-node attention logits (layer 1, fp16 h1) --------------
__global__ void alpha1_kernel(const float* __restrict__ asrc,
                              const float* __restrict__ adst) {
    int warp = (blockIdx.x * blockDim.x + threadIdx.x) >> 5;
    int lane = threadIdx.x & 31;
    if (warp >= NN) return;
    const __half* row = g_h1h + (size_t)warp * HC;
    float ps[HEADS], pd[HEADS];
#pragma unroll
    for (int h = 0; h < HEADS; h++) { ps[h] = 0.f; pd[h] = 0.f; }
#pragma unroll
    for (int h = 0; h < HEADS; h++) {
        int idx = h * 128 + lane * 4;
        uint2 pk = *(const uint2*)&row[idx];
        float2 p0 = __half22float2(*(__half2*)&pk.x);
        float2 p1 = __half22float2(*(__half2*)&pk.y);
        ps[h] += p0.x * asrc[idx]     + p0.y * asrc[idx + 1]
               + p1.x * asrc[idx + 2] + p1.y * asrc[idx + 3];
        pd[h] += p0.x * adst[idx]     + p0.y * adst[idx + 1]
               + p1.x * adst[idx + 2] + p1.y * adst[idx + 3];
    }
#pragma unroll
    for (int off = 16; off; off >>= 1)
#pragma unroll
        for (int h = 0; h < HEADS; h++) {
            ps[h] += __shfl_xor_sync(0xffffffffu, ps[h], off);
            pd[h] += __shfl_xor_sync(0xffffffffu, pd[h], off);
        }
    if (lane == 0)
#pragma unroll
        for (int h = 0; h < HEADS; h++) {
            g_as1[warp * HEADS + h] = ps[h];
            g_ad1[warp * HEADS + h] = pd[h];
        }
}

// ------- fused layer-1 softmax + aggregate: 4 warps per node, fp16 gather ---
__global__ __launch_bounds__(256) void fused_agg1() {
    int gw   = (blockIdx.x * blockDim.x + threadIdx.x) >> 5;
    int lane = threadIdx.x & 31;
    int d    = gw >> 2;
    int h    = gw & 3;
    if (d >= NN) return;
    const int beg = g_off[d], end = g_off[d + 1];
    const int deg = end - beg;
    const float ad = g_ad1[d * 4 + h];

    float den;
    float a0 = 0.f, a1 = 0.f, a2 = 0.f, a3 = 0.f;

    auto gather = [&](float w, int s) {
        const uint2* rp = (const uint2*)(g_h1h + (size_t)s * HC + h * 128) + lane;
        uint2 pk = *rp;
        float2 p0 = __half22float2(*(__half2*)&pk.x);
        float2 p1 = __half22float2(*(__half2*)&pk.y);
        a0 += w * p0.x; a1 += w * p0.y;
        a2 += w * p1.x; a3 += w * p1.y;
    };

    if (deg <= 32) {
        int   s_l = (lane < deg) ? g_esrc[beg + lane] : 0;
        float e_l = (lane < deg) ? lrelu(g_as1[s_l * 4 + h] + ad) : -1e30f;
        float m = e_l;
#pragma unroll
        for (int off = 16; off; off >>= 1)
            m = fmaxf(m, __shfl_xor_sync(0xffffffffu, m, off));
        float w_l = (lane < deg) ? __expf(e_l - m) : 0.f;
        den = w_l;
#pragma unroll
        for (int off = 16; off; off >>= 1)
            den += __shfl_xor_sync(0xffffffffu, den, off);
#pragma unroll 8
        for (int j = 0; j < deg; j++) {
            float w = __shfl_sync(0xffffffffu, w_l, j);
            int   s = __shfl_sync(0xffffffffu, s_l, j);
            gather(w, s);
        }
    } else {
        float m = -1e30f;
        for (int i = beg + lane; i < end; i += 32)
            m = fmaxf(m, lrelu(g_as1[g_esrc[i] * 4 + h] + ad));
#pragma unroll
        for (int off = 16; off; off >>= 1)
            m = fmaxf(m, __shfl_xor_sync(0xffffffffu, m, off));
        den = 0.f;
        for (int base = beg; base < end; base += 32) {
            int   idx = base + lane;
            int   s_l = (idx < end) ? g_esrc[idx] : 0;
            float w_l = (idx < end)
                      ? __expf(lrelu(g_as1[s_l * 4 + h] + ad) - m) : 0.f;
            den += w_l;
            int n = min(32, end - base);
#pragma unroll 8
            for (int j = 0; j < n; j++) {
                float w = __shfl_sync(0xffffffffu, w_l, j);
                int   s = __shfl_sync(0xffffffffu, s_l, j);
                gather(w, s);
            }
        }
#pragma unroll
        for (int off = 16; off; off >>= 1)
            den += __shfl_xor_sync(0xffffffffu, den, off);
    }
    const float r = 1.f / den;
    float4 o = make_float4(a0 * r, a1 * r, a2 * r, a3 * r);
    ((float4*)g_out1)[(size_t)d * 128 + h * 32 + lane] = o;
}

// --------- ELU + tiny GEMM2 (512x6) + layer-2 logits ------------------------
__global__ void elu_gemm2_kernel(const float* __restrict__ b1,
                                 const float* __restrict__ W2,
                                 const float* __restrict__ asrc2,
                                 const float* __restrict__ adst2) {
    int warp = (blockIdx.x * blockDim.x + threadIdx.x) >> 5;
    int lane = threadIdx.x & 31;
    if (warp >= NN) return;
    const float* row = g_out1 + (size_t)warp * HC;
    float acc[CLS];
#pragma unroll
    for (int c = 0; c < CLS; c++) acc[c] = 0.f;
#pragma unroll
    for (int i = 0; i < 16; i++) {
        int k = lane + 32 * i;
        float a = row[k] + b1[k];
        a = a > 0.f ? a : (__expf(a) - 1.f);
#pragma unroll
        for (int c = 0; c < CLS; c++) acc[c] += a * W2[k * CLS + c];
    }
#pragma unroll
    for (int off = 16; off; off >>= 1)
#pragma unroll
        for (int c = 0; c < CLS; c++)
            acc[c] += __shfl_xor_sync(0xffffffffu, acc[c], off);
    if (lane == 0) {
        float s2 = 0.f, d2 = 0.f;
#pragma unroll
        for (int c = 0; c < CLS; c++) {
            g_h2[warp * CLS + c] = acc[c];
            s2 += acc[c] * asrc2[c];
            d2 += acc[c] * adst2[c];
        }
        g_as2[warp] = s2;
        g_ad2[warp] = d2;
    }
}

// ------------- fused layer-2 softmax + aggregate ----------------------------
__global__ __launch_bounds__(256) void fused_agg2(const float* __restrict__ b2,
                                                  float* __restrict__ out) {
    int d    = (blockIdx.x * blockDim.x + threadIdx.x) >> 5;
    int lane = threadIdx.x & 31;
    if (d >= NN) return;
    const int beg = g_off[d], end = g_off[d + 1];
    const float ad = g_ad2[d];

    float m = -1e30f;
    for (int i = beg + lane; i < end; i += 32)
        m = fmaxf(m, lrelu(g_as2[g_esrc[i]] + ad));
#pragma unroll
    for (int off = 16; off; off >>= 1)
        m = fmaxf(m, __shfl_xor_sync(0xffffffffu, m, off));

    float den = 0.f;
    float acc[CLS];
#pragma unroll
    for (int c = 0; c < CLS; c++) acc[c] = 0.f;
    for (int i = beg + lane; i < end; i += 32) {
        int s = g_esrc[i];
        float w = __expf(lrelu(g_as2[s] + ad) - m);
        den += w;
#pragma unroll
        for (int c = 0; c < CLS; c++) acc[c] += w * g_h2[s * CLS + c];
    }
#pragma unroll
    for (int off = 16; off; off >>= 1) {
        den += __shfl_xor_sync(0xffffffffu, den, off);
#pragma unroll
        for (int c = 0; c < CLS; c++)
            acc[c] += __shfl_xor_sync(0xffffffffu, acc[c], off);
    }
    if (lane == 0) {
        float rden = 1.f / den;
#pragma unroll
        for (int c = 0; c < CLS; c++)
            out[d * CLS + c] = acc[c] * rden + b2[c];
    }
}

// ---------------- launch ----------------------------------------------------
extern "C" void kernel_launch(void* const* d_in, const int* in_sizes, int n_in,
                              void* d_out, int out_size) {
    const float* x     = (const float*)d_in[0];
    const int*   ei    = (const int*)d_in[1];
    const float* W1    = (const float*)d_in[2];
    const float* asrc1 = (const float*)d_in[3];
    const float* adst1 = (const float*)d_in[4];
    const float* b1    = (const float*)d_in[5];
    const float* W2    = (const float*)d_in[6];
    const float* asrc2 = (const float*)d_in[7];
    const float* adst2 = (const float*)d_in[8];
    const float* b2    = (const float*)d_in[9];
    float* out = (float*)d_out;

    static cudaStream_t s2 = nullptr;
    static cudaEvent_t  e1 = nullptr, e2 = nullptr;
    if (!s2) {
        cudaStreamCreateWithFlags(&s2, cudaStreamNonBlocking);
        cudaEventCreateWithFlags(&e1, cudaEventDisableTiming);
        cudaEventCreateWithFlags(&e2, cudaEventDisableTiming);
        cudaFuncSetAttribute(gemm1_tc,
                             cudaFuncAttributeMaxDynamicSharedMemorySize, SMEM_BYTES);
    }

    // fork: CSR build on side stream, overlapped with w1t + GEMM
    cudaEventRecord(e1, 0);
    cudaStreamWaitEvent(s2, e1, 0);
    zero_deg_kernel<<<(NN + 255) / 256, 256, 0, s2>>>();
    count_kernel<<<(ET + 255) / 256, 256, 0, s2>>>(ei);
    scan_kernel<<<1, 1024, 0, s2>>>();
    scatter_kernel<<<(ET + 255) / 256, 256, 0, s2>>>(ei);
    cudaEventRecord(e2, s2);

    w1t_kernel<<<dim3(HC / 32, FIN / 32), 256>>>(W1);
    gemm1_tc<<<dim3(HC / BN, (NN + BM - 1) / BM), 256, SMEM_BYTES>>>(x);
    alpha1_kernel<<<(NN * 32 + 255) / 256, 256>>>(asrc1, adst1);

    // join: aggregation needs CSR + logits
    cudaStreamWaitEvent(0, e2, 0);
    fused_agg1<<<(NN * 128 + 255) / 256, 256>>>();
    elu_gemm2_kernel<<<(NN * 32 + 255) / 256, 256>>>(b1, W2, asrc2, adst2);
    fused_agg2<<<(NN * 32 + 255) / 256, 256>>>(b2, out);
}

// round 16
// speedup vs baseline: 1.0759x; 1.0759x over previous
#include <cuda_runtime.h>
#include <cuda_bf16.h>
#include <cuda_fp16.h>
#include <math.h>
#include <stdint.h>

#define NN 30000
#define EE 480000
#define ET (EE + NN)
#define FIN 4096
#define HC 512
#define HEADS 4
#define HID 128
#define CLS 6

// ---------------- scratch (static device globals) ---------------------------
__device__ __half   g_h1h[(size_t)NN * HC];    // fp16 h1 (sole copy)
__device__ float    g_out1[(size_t)NN * HC];
__device__ __half   g_w1h[(size_t)HC * FIN];   // W1^T, fp16, K-major
__device__ float    g_as1[NN * HEADS];
__device__ float    g_ad1[NN * HEADS];
__device__ float    g_h2[NN * CLS];
__device__ float    g_as2[NN];
__device__ float    g_ad2[NN];
__device__ int      g_deg[NN];
__device__ int      g_off[NN + 1];
__device__ int      g_pos[NN];
__device__ int      g_esrc[ET];

__device__ __forceinline__ float lrelu(float v) { return v > 0.f ? v : 0.2f * v; }
__device__ __forceinline__ void edge_sd(const int* __restrict__ ei, int e,
                                        int& s, int& d) {
    if (e < EE) { s = ei[e]; d = ei[EE + e]; } else { s = d = e - EE; }
}
__device__ __forceinline__ uint32_t smem_u32(const void* p) {
    uint32_t a;
    asm("{ .reg .u64 t; cvta.to.shared.u64 t, %1; cvt.u32.u64 %0, t; }"
        : "=r"(a) : "l"(p));
    return a;
}
__device__ __forceinline__ void cp16(uint32_t saddr, const void* g, int bytes) {
    asm volatile("cp.async.ca.shared.global [%0], [%1], 16, %2;"
                 :: "r"(saddr), "l"(g), "r"(bytes));
}
__device__ __forceinline__ unsigned pack_h2(float lo, float hi) {
    unsigned d;
    asm("cvt.rn.f16x2.f32 %0, %1, %2;" : "=r"(d) : "f"(hi), "f"(lo));
    return d;
}

// ---------------- CSR build --------------------------------------------------
__global__ void zero_deg_kernel() {
    int i = blockIdx.x * blockDim.x + threadIdx.x;
    if (i < NN) g_deg[i] = 0;
}
__global__ void count_kernel(const int* __restrict__ ei) {
    int e = blockIdx.x * blockDim.x + threadIdx.x;
    if (e >= ET) return;
    int s, d; edge_sd(ei, e, s, d);
    atomicAdd(&g_deg[d], 1);
}
__global__ void scan_kernel() {
    __shared__ int partial[1024];
    const int t = threadIdx.x;
    const int CH = (NN + 1023) / 1024;
    const int base = t * CH;
    int sum = 0;
    for (int c = 0; c < CH; c++) { int i = base + c; if (i < NN) sum += g_deg[i]; }
    partial[t] = sum;
    __syncthreads();
    for (int off = 1; off < 1024; off <<= 1) {
        int v = (t >= off) ? partial[t - off] : 0;
        __syncthreads();
        partial[t] += v;
        __syncthreads();
    }
    int acc = partial[t] - sum;
    for (int c = 0; c < CH; c++) {
        int i = base + c;
        if (i < NN) { g_off[i] = acc; g_pos[i] = acc; acc += g_deg[i]; }
    }
    if (t == 0) g_off[NN] = ET;
}
__global__ void scatter_kernel(const int* __restrict__ ei) {
    int e = blockIdx.x * blockDim.x + threadIdx.x;
    if (e >= ET) return;
    int s, d; edge_sd(ei, e, s, d);
    int p = atomicAdd(&g_pos[d], 1);
    g_esrc[p] = s;
}

// ---------- transpose W1 -> fp16 (32x32 shared tiles, coalesced) ------------
__global__ __launch_bounds__(256) void w1t_kernel(const float* __restrict__ W1) {
    __shared__ float tile[32][33];
    const int k0 = blockIdx.y * 32;
    const int n0 = blockIdx.x * 32;
    const int tx = threadIdx.x & 31;
    const int ty = threadIdx.x >> 5;
#pragma unroll
    for (int r = 0; r < 4; r++) {
        int k = k0 + ty + r * 8;
        tile[ty + r * 8][tx] = W1[(size_t)k * HC + n0 + tx];
    }
    __syncthreads();
#pragma unroll
    for (int r = 0; r < 4; r++) {
        int n = n0 + ty + r * 8;
        g_w1h[(size_t)n * FIN + k0 + tx] = __float2half_rn(tile[tx][ty + r * 8]);
    }
}

// ---------------- GEMM1 (mma.sync fp16): h1 = x @ W1 ------------------------
// CTA 128x256, BK=32, 3-stage cp.async, 8 warps, warp 64x64, mma m16n8k16. (R14)
#define BM 128
#define BN 256
#define BK2 32
#define ASTR 36                      // A row stride, floats
#define BSTRH 40                     // B row stride, halves (80 B, 16B-aligned)
#define A_STAGE (BM * ASTR)          // floats
#define B_STAGE_H (BN * BSTRH)       // halves
#define SMEM_BYTES (3 * (A_STAGE * 4 + B_STAGE_H * 2))   // 116736

__global__ __launch_bounds__(256, 1) void gemm1_tc(const float* __restrict__ A) {
    extern __shared__ float sm[];
    float*  Asm  = sm;
    __half* Bsmh = (__half*)(sm + 3 * A_STAGE);
    const int t    = threadIdx.x;
    const int m0   = blockIdx.y * BM;
    const int n0   = blockIdx.x * BN;
    const int wid  = t >> 5;
    const int lane = t & 31;
    const int gid  = lane >> 2;
    const int tid4 = lane & 3;
    const int wm   = (wid >> 2) * 64;
    const int wn   = (wid & 3) * 64;

    float acc[4][8][4];
#pragma unroll
    for (int i = 0; i < 4; i++)
#pragma unroll
        for (int j = 0; j < 8; j++)
#pragma unroll
            for (int r = 0; r < 4; r++) acc[i][j][r] = 0.f;

    auto load_stage = [&](int s, int k0) {
        uint32_t ab = smem_u32(Asm + s * A_STAGE);
        uint32_t bb = smem_u32(Bsmh + s * B_STAGE_H);
#pragma unroll
        for (int j = 0; j < 4; j++) {
            int idx = j * 256 + t;
            int row = idx >> 3, c4 = (idx & 7) << 2;
            int gr = m0 + row;
            cp16(ab + (row * ASTR + c4) * 4,
                 A + (size_t)gr * FIN + k0 + c4, gr < NN ? 16 : 0);
        }
#pragma unroll
        for (int j = 0; j < 4; j++) {
            int idx = j * 256 + t;
            int row = idx >> 2, c8 = (idx & 3) << 3;
            cp16(bb + (row * BSTRH + c8) * 2,
                 g_w1h + (size_t)(n0 + row) * FIN + k0 + c8, 16);
        }
        asm volatile("cp.async.commit_group;");
    };

    load_stage(0, 0);
    load_stage(1, BK2);

    const int NT = FIN / BK2;
    for (int kt = 0; kt < NT; kt++) {
        if (kt + 1 < NT) asm volatile("cp.async.wait_group 1;");
        else             asm volatile("cp.async.wait_group 0;");
        __syncthreads();
        const int s = kt % 3;
        const float*  as = Asm  + s * A_STAGE;
        const __half* bs = Bsmh + s * B_STAGE_H;

#pragma unroll
        for (int kk = 0; kk < BK2; kk += 16) {
            unsigned af[4][4], bf[8][2];
#pragma unroll
            for (int mt = 0; mt < 4; mt++) {
                int r = wm + mt * 16 + gid;
                float2 v0 = *(const float2*)&as[r * ASTR + kk + tid4 * 2];
                float2 v1 = *(const float2*)&as[(r + 8) * ASTR + kk + tid4 * 2];
                float2 v2 = *(const float2*)&as[r * ASTR + kk + 8 + tid4 * 2];
                float2 v3 = *(const float2*)&as[(r + 8) * ASTR + kk + 8 + tid4 * 2];
                af[mt][0] = pack_h2(v0.x, v0.y);
                af[mt][1] = pack_h2(v1.x, v1.y);
                af[mt][2] = pack_h2(v2.x, v2.y);
                af[mt][3] = pack_h2(v3.x, v3.y);
            }
#pragma unroll
            for (int nt = 0; nt < 8; nt++) {
                int c = wn + nt * 8 + gid;
                bf[nt][0] = *(const unsigned*)&bs[c * BSTRH + kk + tid4 * 2];
                bf[nt][1] = *(const unsigned*)&bs[c * BSTRH + kk + 8 + tid4 * 2];
            }
#pragma unroll
            for (int mt = 0; mt < 4; mt++)
#pragma unroll
                for (int nt = 0; nt < 8; nt++) {
                    asm volatile(
                        "mma.sync.aligned.m16n8k16.row.col.f32.f16.f16.f32 "
                        "{%0,%1,%2,%3}, {%4,%5,%6,%7}, {%8,%9}, {%0,%1,%2,%3};"
                        : "+f"(acc[mt][nt][0]), "+f"(acc[mt][nt][1]),
                          "+f"(acc[mt][nt][2]), "+f"(acc[mt][nt][3])
                        : "r"(af[mt][0]), "r"(af[mt][1]),
                          "r"(af[mt][2]), "r"(af[mt][3]),
                          "r"(bf[nt][0]), "r"(bf[nt][1]));
                }
        }
        if (kt + 2 < NT) load_stage((kt + 2) % 3, (kt + 2) * BK2);
    }

    // epilogue: fp16-only h1 store
#pragma unroll
    for (int mt = 0; mt < 4; mt++) {
        int r1 = m0 + wm + mt * 16 + gid;
        int r2 = r1 + 8;
#pragma unroll
        for (int nt = 0; nt < 8; nt++) {
            int c = n0 + wn + nt * 8 + tid4 * 2;
            if (r1 < NN)
                *(unsigned*)(g_h1h + (size_t)r1 * HC + c) =
                    pack_h2(acc[mt][nt][0], acc[mt][nt][1]);
            if (r2 < NN)
                *(unsigned*)(g_h1h + (size_t)r2 * HC + c) =
                    pack_h2(acc[mt][nt][2], acc[mt][nt][3]);
        }
    }
}

// ---------------- per-node attention logits (layer 1, fp16 h1) --------------
__global__ void alpha1_kernel(const float* __restrict__ asrc,
                              const float* __restrict__ adst) {
    int warp = (blockIdx.x * blockDim.x + threadIdx.x) >> 5;
    int lane = threadIdx.x & 31;
    if (warp >= NN) return;
    const __half* row = g_h1h + (size_t)warp * HC;
    float ps[HEADS], pd[HEADS];
#pragma unroll
    for (int h = 0; h < HEADS; h++) { ps[h] = 0.f; pd[h] = 0.f; }
#pragma unroll
    for (int h = 0; h < HEADS; h++) {
        int idx = h * 128 + lane * 4;
        uint2 pk = *(const uint2*)&row[idx];
        float2 p0 = __half22float2(*(__half2*)&pk.x);
        float2 p1 = __half22float2(*(__half2*)&pk.y);
        ps[h] += p0.x * asrc[idx]     + p0.y * asrc[idx + 1]
               + p1.x * asrc[idx + 2] + p1.y * asrc[idx + 3];
        pd[h] += p0.x * adst[idx]     + p0.y * adst[idx + 1]
               + p1.x * adst[idx + 2] + p1.y * adst[idx + 3];
    }
#pragma unroll
    for (int off = 16; off; off >>= 1)
#pragma unroll
        for (int h = 0; h < HEADS; h++) {
            ps[h] += __shfl_xor_sync(0xffffffffu, ps[h], off);
            pd[h] += __shfl_xor_sync(0xffffffffu, pd[h], off);
        }
    if (lane == 0)
#pragma unroll
        for (int h = 0; h < HEADS; h++) {
            g_as1[warp * HEADS + h] = ps[h];
            g_ad1[warp * HEADS + h] = pd[h];
        }
}

// ------- fused layer-1 softmax + aggregate: 4 warps per node, fp16 gather ---
__global__ __launch_bounds__(256) void fused_agg1() {
    int gw   = (blockIdx.x * blockDim.x + threadIdx.x) >> 5;
    int lane = threadIdx.x & 31;
    int d    = gw >> 2;
    int h    = gw & 3;
    if (d >= NN) return;
    const int beg = g_off[d], end = g_off[d + 1];
    const int deg = end - beg;
    const float ad = g_ad1[d * 4 + h];

    float den;
    float a0 = 0.f, a1 = 0.f, a2 = 0.f, a3 = 0.f;

    auto gather = [&](float w, int s) {
        const uint2* rp = (const uint2*)(g_h1h + (size_t)s * HC + h * 128) + lane;
        uint2 pk = *rp;
        float2 p0 = __half22float2(*(__half2*)&pk.x);
        float2 p1 = __half22float2(*(__half2*)&pk.y);
        a0 += w * p0.x; a1 += w * p0.y;
        a2 += w * p1.x; a3 += w * p1.y;
    };

    if (deg <= 32) {
        int   s_l = (lane < deg) ? g_esrc[beg + lane] : 0;
        float e_l = (lane < deg) ? lrelu(g_as1[s_l * 4 + h] + ad) : -1e30f;
        float m = e_l;
#pragma unroll
        for (int off = 16; off; off >>= 1)
            m = fmaxf(m, __shfl_xor_sync(0xffffffffu, m, off));
        float w_l = (lane < deg) ? __expf(e_l - m) : 0.f;
        den = w_l;
#pragma unroll
        for (int off = 16; off; off >>= 1)
            den += __shfl_xor_sync(0xffffffffu, den, off);
#pragma unroll 8
        for (int j = 0; j < deg; j++) {
            float w = __shfl_sync(0xffffffffu, w_l, j);
            int   s = __shfl_sync(0xffffffffu, s_l, j);
            gather(w, s);
        }
    } else {
        float m = -1e30f;
        for (int i = beg + lane; i < end; i += 32)
            m = fmaxf(m, lrelu(g_as1[g_esrc[i] * 4 + h] + ad));
#pragma unroll
        for (int off = 16; off; off >>= 1)
            m = fmaxf(m, __shfl_xor_sync(0xffffffffu, m, off));
        den = 0.f;
        for (int base = beg; base < end; base += 32) {
            int   idx = base + lane;
            int   s_l = (idx < end) ? g_esrc[idx] : 0;
            float w_l = (idx < end)
                      ? __expf(lrelu(g_as1[s_l * 4 + h] + ad) - m) : 0.f;
            den += w_l;
            int n = min(32, end - base);
#pragma unroll 8
            for (int j = 0; j < n; j++) {
                float w = __shfl_sync(0xffffffffu, w_l, j);
                int   s = __shfl_sync(0xffffffffu, s_l, j);
                gather(w, s);
            }
        }
#pragma unroll
        for (int off = 16; off; off >>= 1)
            den += __shfl_xor_sync(0xffffffffu, den, off);
    }
    const float r = 1.f / den;
    float4 o = make_float4(a0 * r, a1 * r, a2 * r, a3 * r);
    ((float4*)g_out1)[(size_t)d * 128 + h * 32 + lane] = o;
}

// --------- ELU + tiny GEMM2 (512x6) + layer-2 logits ------------------------
__global__ void elu_gemm2_kernel(const float* __restrict__ b1,
                                 const float* __restrict__ W2,
                                 const float* __restrict__ asrc2,
                                 const float* __restrict__ adst2) {
    int warp = (blockIdx.x * blockDim.x + threadIdx.x) >> 5;
    int lane = threadIdx.x & 31;
    if (warp >= NN) return;
    const float* row = g_out1 + (size_t)warp * HC;
    float acc[CLS];
#pragma unroll
    for (int c = 0; c < CLS; c++) acc[c] = 0.f;
#pragma unroll
    for (int i = 0; i < 16; i++) {
        int k = lane + 32 * i;
        float a = row[k] + b1[k];
        a = a > 0.f ? a : (__expf(a) - 1.f);
#pragma unroll
        for (int c = 0; c < CLS; c++) acc[c] += a * W2[k * CLS + c];
    }
#pragma unroll
    for (int off = 16; off; off >>= 1)
#pragma unroll
        for (int c = 0; c < CLS; c++)
            acc[c] += __shfl_xor_sync(0xffffffffu, acc[c], off);
    if (lane == 0) {
        float s2 = 0.f, d2 = 0.f;
#pragma unroll
        for (int c = 0; c < CLS; c++) {
            g_h2[warp * CLS + c] = acc[c];
            s2 += acc[c] * asrc2[c];
            d2 += acc[c] * adst2[c];
        }
        g_as2[warp] = s2;
        g_ad2[warp] = d2;
    }
}

// ------------- fused layer-2 softmax + aggregate ----------------------------
__global__ __launch_bounds__(256) void fused_agg2(const float* __restrict__ b2,
                                                  float* __restrict__ out) {
    int d    = (blockIdx.x * blockDim.x + threadIdx.x) >> 5;
    int lane = threadIdx.x & 31;
    if (d >= NN) return;
    const int beg = g_off[d], end = g_off[d + 1];
    const float ad = g_ad2[d];

    float m = -1e30f;
    for (int i = beg + lane; i < end; i += 32)
        m = fmaxf(m, lrelu(g_as2[g_esrc[i]] + ad));
#pragma unroll
    for (int off = 16; off; off >>= 1)
        m = fmaxf(m, __shfl_xor_sync(0xffffffffu, m, off));

    float den = 0.f;
    float acc[CLS];
#pragma unroll
    for (int c = 0; c < CLS; c++) acc[c] = 0.f;
    for (int i = beg + lane; i < end; i += 32) {
        int s = g_esrc[i];
        float w = __expf(lrelu(g_as2[s] + ad) - m);
        den += w;
#pragma unroll
        for (int c = 0; c < CLS; c++) acc[c] += w * g_h2[s * CLS + c];
    }
#pragma unroll
    for (int off = 16; off; off >>= 1) {
        den += __shfl_xor_sync(0xffffffffu, den, off);
#pragma unroll
        for (int c = 0; c < CLS; c++)
            acc[c] += __shfl_xor_sync(0xffffffffu, acc[c], off);
    }
    if (lane == 0) {
        float rden = 1.f / den;
#pragma unroll
        for (int c = 0; c < CLS; c++)
            out[d * CLS + c] = acc[c] * rden + b2[c];
    }
}

// ---------------- launch ----------------------------------------------------
extern "C" void kernel_launch(void* const* d_in, const int* in_sizes, int n_in,
                              void* d_out, int out_size) {
    const float* x     = (const float*)d_in[0];
    const int*   ei    = (const int*)d_in[1];
    const float* W1    = (const float*)d_in[2];
    const float* asrc1 = (const float*)d_in[3];
    const float* adst1 = (const float*)d_in[4];
    const float* b1    = (const float*)d_in[5];
    const float* W2    = (const float*)d_in[6];
    const float* asrc2 = (const float*)d_in[7];
    const float* adst2 = (const float*)d_in[8];
    const float* b2    = (const float*)d_in[9];
    float* out = (float*)d_out;

    static cudaStream_t s2 = nullptr;
    static cudaEvent_t  e1 = nullptr, e2 = nullptr;
    if (!s2) {
        cudaStreamCreateWithFlags(&s2, cudaStreamNonBlocking);
        cudaEventCreateWithFlags(&e1, cudaEventDisableTiming);
        cudaEventCreateWithFlags(&e2, cudaEventDisableTiming);
        cudaFuncSetAttribute(gemm1_tc,
                             cudaFuncAttributeMaxDynamicSharedMemorySize, SMEM_BYTES);
    }

    // fork: CSR build on side stream, overlapped with w1t + GEMM
    cudaEventRecord(e1, 0);
    cudaStreamWaitEvent(s2, e1, 0);
    zero_deg_kernel<<<(NN + 255) / 256, 256, 0, s2>>>();
    count_kernel<<<(ET + 255) / 256, 256, 0, s2>>>(ei);
    scan_kernel<<<1, 1024, 0, s2>>>();
    scatter_kernel<<<(ET + 255) / 256, 256, 0, s2>>>(ei);
    cudaEventRecord(e2, s2);

    w1t_kernel<<<dim3(HC / 32, FIN / 32), 256>>>(W1);
    gemm1_tc<<<dim3(HC / BN, (NN + BM - 1) / BM), 256, SMEM_BYTES>>>(x);
    alpha1_kernel<<<(NN * 32 + 255) / 256, 256>>>(asrc1, adst1);

    // join: aggregation needs CSR + logits
    cudaStreamWaitEvent(0, e2, 0);
    fused_agg1<<<(NN * 128 + 255) / 256, 256>>>();
    elu_gemm2_kernel<<<(NN * 32 + 255) / 256, 256>>>(b1, W2, asrc2, adst2);
    fused_agg2<<<(NN * 32 + 255) / 256, 256>>>(b2, out);
}